// round 9
// baseline (speedup 1.0000x reference)
#include <cuda_runtime.h>
#include <math.h>

#define NEGF    (-1e30f)
#define MAXB    16
#define NCH     32
#define LOG2E_F 1.4426950408889634f
#define LN2_F   0.6931471805599453f

// Scratch (static device arrays; no allocations allowed)
__device__ float    g_num[MAXB];                 // numerator logZ per batch (natural log)
__device__ float    g_LP[MAXB * NCH * 8 * 8];    // [b][c][j][i] log chunk matrices
__device__ unsigned g_done = 0;

// ---------------- helpers ----------------
__device__ __forceinline__ float ex2f_(float x) {
    float r; asm("ex2.approx.ftz.f32 %0, %1;" : "=f"(r) : "f"(x)); return r;
}
__device__ __forceinline__ float lg2f_(float x) {
    float r; asm("lg2.approx.ftz.f32 %0, %1;" : "=f"(r) : "f"(x)); return r;
}
// logaddexp in log2 domain: log2(2^a + 2^b)
__device__ __forceinline__ float lae2(float a, float b) {
    float m = fmaxf(a, b);
    float d = fminf(a, b) - m;            // <= 0
    return m + lg2f_(1.0f + ex2f_(d));
}

// ---- numerator step: thread owns 8 consecutive targets, 16 linear values ----
// Lanes computed DESCENDING so the shfl result (thread boundary) is consumed
// last -> shfl latency hidden. EMU = emission buffer for frame T_,
// EMN = buffer to prefetch frame T_+2 into.
#define NSTEP(T_, EMU, EMN) do {                                              \
    float pe_ = __shfl_up_sync(0xffffffffu, ae[7], 1);                        \
    float px_ = __shfl_up_sync(0xffffffffu, ax[7], 1);                        \
    _Pragma("unroll")                                                         \
    for (int j = 7; j >= 1; --j) {                                            \
        float nae_ = EMU[j].x * fmaf(ae[j-1], tee[j], ax[j-1] * txe[j]);      \
        float nax_ = EMU[j].y * fmaf(ae[j],   tex[j], ax[j]   * txx[j]);      \
        ae[j] = nae_; ax[j] = nax_;                                           \
    }                                                                         \
    {                                                                         \
        float nax0_ = EMU[0].y * fmaf(ae[0], tex[0], ax[0] * txx[0]);         \
        ae[0] = EMU[0].x * fmaf(pe_, tee0e, px_ * txe0e);                     \
        ax[0] = nax0_;                                                        \
    }                                                                         \
    int fp_ = min((T_) + 2, lenm1);                                           \
    const float* tp_ = tab + fp_ * 8;                                         \
    _Pragma("unroll")                                                         \
    for (int j = 0; j < 8; ++j)                                               \
        EMN[j] = *(const float2*)(tp_ + so[j]);                               \
} while (0)

// ---- rescale + frame sync (every 2 steps; warp-lockstep schedule) ----
// Per-thread block exponent e (value = v * 2^e). Incoming-frame conversion is
// folded into the boundary transition constants; zero threads (frontier
// suffix) adopt the upstream frame.
#define NRESC() do {                                                          \
    float m_ = 0.f;                                                           \
    _Pragma("unroll")                                                         \
    for (int j = 0; j < 8; ++j) m_ = fmaxf(m_, fmaxf(ae[j], ax[j]));          \
    int mb_ = __float_as_int(m_);                                             \
    int ei_ = (mb_ == 0) ? 0 : ((mb_ >> 23) - 127);                           \
    float fr_ = __int_as_float((127 - ei_) << 23);                            \
    _Pragma("unroll")                                                         \
    for (int j = 0; j < 8; ++j) { ae[j] *= fr_; ax[j] *= fr_; }               \
    int en_  = e + ei_;                                                       \
    int pei_ = __shfl_up_sync(0xffffffffu, en_, 1);                           \
    e = (mb_ == 0 && lane > 0) ? pei_ : en_;                                  \
    int d_  = pei_ - e;                                                       \
    int dc_ = min(max(d_, -126), 90);                                         \
    float fi_ = __int_as_float((dc_ + 127) << 23);                            \
    tee0e = tee0b * fi_; txe0e = txe0b * fi_;                                 \
} while (0)

extern "C" __global__ void __launch_bounds__(256, 1)
ctccrf_fused(const float* __restrict__ em,      // (B,T,8)
             const float* __restrict__ trans,   // (8,8)
             const float* __restrict__ bos,     // (8)
             const float* __restrict__ eos,     // (8)
             const int*   __restrict__ lengths, // (B)
             const int*   __restrict__ targets, // (B,L)
             const int*   __restrict__ tlens,   // (B)
             float* __restrict__ out,
             int B, int T, int L)
{
    extern __shared__ char dsm[];
    __shared__ float s_scratch[MAXB];
    __shared__ int   s_flag;
    const int tid = threadIdx.x;
    float* tab = (float*)dsm;                   // [T][8] exp-emission table

    if ((int)blockIdx.x < B) {
        const int b = blockIdx.x;
        // ---------- Emission table fill: all 256 threads ----------
        {
            const float* emb = em + (size_t)b * T * 8;
            for (int f = tid; f < T; f += 256) {
                float4 lo = __ldg((const float4*)(emb + f * 8));
                float4 hi = __ldg((const float4*)(emb + f * 8 + 4));
                float v0 = ex2f_(lo.x * LOG2E_F), v1 = ex2f_(lo.y * LOG2E_F);
                float v2 = ex2f_(lo.z * LOG2E_F), v3 = ex2f_(lo.w * LOG2E_F);
                float v4 = ex2f_(hi.x * LOG2E_F), v5 = ex2f_(hi.y * LOG2E_F);
                float v6 = ex2f_(hi.z * LOG2E_F), v7 = ex2f_(hi.w * LOG2E_F);
                // pair-interleaved: [s0,s4, s1,s5, s2,s6, s3,s7]
                *(float4*)(tab + f * 8)     = make_float4(v0, v4, v1, v5);
                *(float4*)(tab + f * 8 + 4) = make_float4(v2, v6, v3, v7);
            }
        }
        __syncthreads();

        if (tid < 32) {
            // ------- Numerator: ONE warp, 8 targets/thread, no inter-warp sync -------
            const int lane = tid;
            const int len = lengths[b];
            const int lenm1 = len - 1;

            int   so[8];
            float tee[8], txe[8], tex[8], txx[8];
            int tg0 = 0;
            #pragma unroll
            for (int j = 0; j < 8; ++j) {
                const int u  = lane * 8 + j;
                const int tg = __ldg(targets + b * L + u);
                if (j == 0) tg0 = tg;
                so[j] = 2 * tg;
                const int tgp = (u == 0) ? tg : __ldg(targets + b * L + u - 1);
                tee[j] = __expf(__ldg(trans + tgp * 8 + tg));
                txe[j] = __expf(__ldg(trans + (tgp + 4) * 8 + tg));
                tex[j] = __expf(__ldg(trans + tg * 8 + tg + 4));
                txx[j] = __expf(__ldg(trans + (tg + 4) * 8 + tg + 4));
            }
            // boundary (j=0) transitions; lane 0 has no predecessor -> 0
            const float tee0b = (lane == 0) ? 0.f : tee[0];
            const float txe0b = (lane == 0) ? 0.f : txe[0];
            float tee0e = tee0b, txe0e = txe0b;   // frame-adjusted (d=0 at start)

            float ae[8], ax[8];
            #pragma unroll
            for (int j = 0; j < 8; ++j) { ae[j] = 0.f; ax[j] = 0.f; }
            if (lane == 0)
                ae[0] = __expf(__ldg(bos + tg0) + __ldg(em + (size_t)b * T * 8 + tg0));
            int e = 0;

            // emission buffers: emc = frame 1, emn = frame 2 (clamped)
            float2 emc[8], emn[8];
            {
                const float* t1 = tab + min(1, lenm1) * 8;
                const float* t2 = tab + min(2, lenm1) * 8;
                #pragma unroll
                for (int j = 0; j < 8; ++j) {
                    emc[j] = *(const float2*)(t1 + so[j]);
                    emn[j] = *(const float2*)(t2 + so[j]);
                }
            }

            int t = 1;
            for (; t + 1 < len; t += 2) {
                NSTEP(t,     emc, emc);   // use frame t,   prefetch t+2 into emc
                NSTEP(t + 1, emn, emn);   // use frame t+1, prefetch t+3 into emn
                NRESC();
            }
            if (t < len) { NSTEP(t, emc, emc); }   // last step (t = len-1)

            // ---- final logsumexp for the terminal target ----
            const int tl = __ldg(tlens + b);
            const int uf = tl - 1;
            if (lane == (uf >> 3)) {
                const int jf = uf & 7;
                float vE = 0.f, vX = 0.f;
                int esF = 0;
                #pragma unroll
                for (int j = 0; j < 8; ++j)
                    if (j == jf) { vE = ae[j]; vX = ax[j]; esF = so[j] >> 1; }
                float fe2 = (vE > 0.f ? lg2f_(vE) : NEGF) + (float)e
                            + __ldg(eos + esF) * LOG2E_F;
                float fx2 = (vX > 0.f ? lg2f_(vX) : NEGF) + (float)e
                            + __ldg(eos + esF + 4) * LOG2E_F;
                g_num[b] = lae2(fe2, fx2) * LN2_F;
            }
        }
    } else {
        // ------------- Denominator Phase A: chunked 8x8 linear-space scan -------------
        const int db = blockIdx.x - B;          // batch (grid is exactly 2B)
        const int c = tid >> 3;                 // chunk 0..31
        const int i = tid & 7;                  // row of chunk matrix
        const int len = lengths[db];
        const int C = (T - 1 + NCH - 1) / NCH;

        float E[64];
        #pragma unroll
        for (int k = 0; k < 64; ++k) E[k] = __expf(__ldg(trans + k));

        float r[8];
        #pragma unroll
        for (int j = 0; j < 8; ++j) r[j] = (j == i) ? 1.0f : 0.0f;
        float off = 0.0f;

        const int t0 = 1 + c * C;
        const int t1 = min(t0 + C, len);
        const float* emb = em + (size_t)db * T * 8;

        for (int t = t0; t < t1; ++t) {
            float4 lo = __ldg((const float4*)(emb + t * 8));
            float4 hi = __ldg((const float4*)(emb + t * 8 + 4));
            float Em[8];
            Em[0] = __expf(lo.x); Em[1] = __expf(lo.y);
            Em[2] = __expf(lo.z); Em[3] = __expf(lo.w);
            Em[4] = __expf(hi.x); Em[5] = __expf(hi.y);
            Em[6] = __expf(hi.z); Em[7] = __expf(hi.w);

            float s[8];
            #pragma unroll
            for (int j = 0; j < 8; ++j) {
                float acc = r[0] * E[0 * 8 + j];
                #pragma unroll
                for (int kk = 1; kk < 8; ++kk) acc = fmaf(r[kk], E[kk * 8 + j], acc);
                s[j] = acc * Em[j];
            }
            #pragma unroll
            for (int j = 0; j < 8; ++j) r[j] = s[j];

            if (((t - t0) & 3) == 3) {
                float m = r[0];
                #pragma unroll
                for (int j = 1; j < 8; ++j) m = fmaxf(m, r[j]);
                float inv = __fdividef(1.0f, m);
                off += __logf(m);
                #pragma unroll
                for (int j = 0; j < 8; ++j) r[j] *= inv;
            }
        }

        #pragma unroll
        for (int j = 0; j < 8; ++j) {
            float lv = (r[j] > 0.0f) ? (__logf(r[j]) + off) : NEGF;
            g_LP[(((db * NCH) + c) * 8 + j) * 8 + i] = lv;
        }
    }

    // ---------------- Fused finish: last block folds chunks + reduces ----------------
    __threadfence();
    __syncthreads();
    if (tid == 0) {
        unsigned old = atomicAdd(&g_done, 1u);
        s_flag = (old == (unsigned)(2 * B - 1));
    }
    __syncthreads();
    if (s_flag) {
        __threadfence();
        const int  bq = min(tid >> 3, B - 1);   // clamp so all 256 threads run shfls
        const int  j  = tid & 7;
        const bool active = (tid >> 3) < B;

        float alpha = __ldg(bos + j) + __ldg(em + (size_t)bq * T * 8 + j);  // natural log
        const float* base = g_LP + (size_t)bq * NCH * 64 + j * 8;
        float4 plo[4], phi[4];
        #pragma unroll
        for (int kk = 0; kk < 4; ++kk) {
            plo[kk] = __ldg((const float4*)(base + kk * 64));
            phi[kk] = __ldg((const float4*)(base + kk * 64 + 4));
        }
        #pragma unroll 4
        for (int c = 0; c < NCH; ++c) {
            float4 lo = plo[c & 3], hi = phi[c & 3];
            int cn = c + 4;
            if (cn < NCH) {
                plo[c & 3] = __ldg((const float4*)(base + cn * 64));
                phi[c & 3] = __ldg((const float4*)(base + cn * 64 + 4));
            }
            float M[8] = {lo.x, lo.y, lo.z, lo.w, hi.x, hi.y, hi.z, hi.w};
            float v[8], m = -3.0e38f;
            #pragma unroll
            for (int i2 = 0; i2 < 8; ++i2) {
                float ai = __shfl_sync(0xffffffffu, alpha, i2, 8);
                v[i2] = ai + M[i2];
                m = fmaxf(m, v[i2]);
            }
            float s = 0.0f;
            #pragma unroll
            for (int i2 = 0; i2 < 8; ++i2) s += ex2f_((v[i2] - m) * LOG2E_F);
            alpha = m + lg2f_(s) * LN2_F;
        }
        float f = alpha + __ldg(eos + j);
        float m = f;
        #pragma unroll
        for (int d = 4; d >= 1; d >>= 1) m = fmaxf(m, __shfl_xor_sync(0xffffffffu, m, d, 8));
        float s = ex2f_((f - m) * LOG2E_F);
        #pragma unroll
        for (int d = 4; d >= 1; d >>= 1) s += __shfl_xor_sync(0xffffffffu, s, d, 8);
        float den = m + lg2f_(s) * LN2_F;

        if (active && j == 0) s_scratch[tid >> 3] = den - g_num[bq];
        __syncthreads();
        if (tid == 0) {
            float acc = 0.0f;
            for (int bb = 0; bb < B; ++bb) acc += s_scratch[bb];
            out[0] = acc / (float)B;
            g_done = 0;                         // reset for next graph replay
        }
    }
}

extern "C" void kernel_launch(void* const* d_in, const int* in_sizes, int n_in,
                              void* d_out, int out_size)
{
    const float* em     = (const float*)d_in[0];  // (B,T,8)
    const float* trans  = (const float*)d_in[1];  // (8,8)
    const float* bos    = (const float*)d_in[2];  // (8)
    const float* eos    = (const float*)d_in[3];  // (8)
    const int*   lens   = (const int*)  d_in[4];  // (B)
    const int*   tgts   = (const int*)  d_in[5];  // (B,L)
    const int*   tlens  = (const int*)  d_in[6];  // (B)
    float* out = (float*)d_out;

    const int B = in_sizes[4];                 // 16
    const int T = in_sizes[0] / (B * 8);       // 2048
    const int L = in_sizes[5] / B;             // 256

    // dynamic smem: exp-emission table [T][8] float (64 KB for T=2048)
    const size_t smem = (size_t)T * 8 * sizeof(float);
    cudaFuncSetAttribute(ctccrf_fused, cudaFuncAttributeMaxDynamicSharedMemorySize, (int)smem);

    // Blocks [0,B): numerator (single worker warp, 8 targets/thread).
    // Blocks [B,2B): denominator phase A. Last-done block runs the finish fold.
    ctccrf_fused<<<2 * B, 256, smem>>>(em, trans, bos, eos, lens, tgts, tlens, out, B, T, L);
}

// round 10
// speedup vs baseline: 1.3596x; 1.3596x over previous
#include <cuda_runtime.h>
#include <math.h>

#define NEGF    (-1e30f)
#define MAXB    16
#define NCH     32
#define LOG2E_F 1.4426950408889634f
#define LN2_F   0.6931471805599453f

// Scratch (static device arrays; no allocations allowed)
__device__ float    g_num[MAXB];                 // numerator logZ per batch (natural log)
__device__ float    g_LP[MAXB * NCH * 8 * 8];    // [b][c][j][i] log chunk matrices
__device__ unsigned g_done = 0;

// ---------------- helpers ----------------
__device__ __forceinline__ float ex2f_(float x) {
    float r; asm("ex2.approx.ftz.f32 %0, %1;" : "=f"(r) : "f"(x)); return r;
}
__device__ __forceinline__ float lg2f_(float x) {
    float r; asm("lg2.approx.ftz.f32 %0, %1;" : "=f"(r) : "f"(x)); return r;
}
// logaddexp in log2 domain: log2(2^a + 2^b)
__device__ __forceinline__ float lae2(float a, float b) {
    float m = fmaxf(a, b);
    float d = fminf(a, b) - m;            // <= 0
    return m + lg2f_(1.0f + ex2f_(d));
}
__device__ __forceinline__ float4 lds128v(const float4* p) {
    float4 v; unsigned a = (unsigned)__cvta_generic_to_shared(p);
    asm volatile("ld.volatile.shared.v4.f32 {%0,%1,%2,%3},[%4];"
                 : "=f"(v.x), "=f"(v.y), "=f"(v.z), "=f"(v.w) : "r"(a));
    return v;
}
__device__ __forceinline__ void sts128v(float4* p, float4 v) {
    unsigned a = (unsigned)__cvta_generic_to_shared(p);
    asm volatile("st.volatile.shared.v4.f32 [%0],{%1,%2,%3,%4};"
                 :: "r"(a), "f"(v.x), "f"(v.y), "f"(v.z), "f"(v.w));
}
// predicated volatile STS.128 (no BSSY envelope)
__device__ __forceinline__ void sts128v_pred(float4* p, float4 v, int doit) {
    unsigned a = (unsigned)__cvta_generic_to_shared(p);
    asm volatile("{ .reg .pred p0;\n\t"
                 "setp.ne.u32 p0, %0, 0;\n\t"
                 "@p0 st.volatile.shared.v4.f32 [%1],{%2,%3,%4,%5}; }"
                 :: "r"(doit), "r"(a), "f"(v.x), "f"(v.y), "f"(v.z), "f"(v.w));
}
__device__ __forceinline__ int isnanf_(float x) { return x != x; }

// Fold boundary transition constants for slot S_ of the current group:
// scale by 2^(e_src - e).  e_src: lane0 takes the ring slot's exponent (.z),
// other lanes take the previous lane's exponent (eprev_).  Group-constant.
#define FOLD(S_, CZ_) do {                                                     \
    int ez_ = (lane == 0) ? ((warp > 0) ? __float_as_int(CZ_) : e) : eprev_;   \
    int d_ = min(max(ez_ - e, -126), 60);                                      \
    float fi_ = __int_as_float((d_ + 127) << 23);                              \
    teeW[S_] = tee0b * fi_; txeW[S_] = txe0b * fi_;                            \
} while (0)

// One numerator step, LINEAR space. Thread owns targets u0 (even), u1 (odd).
// Per-step chain: shfl + fmaf + mul. Everything else is off-chain.
#define NSTEP(T_, EMB0, EMB1, PE_, PX_, S_) do {                               \
    float pe_ = __shfl_up_sync(0xffffffffu, ae1, 1);                           \
    float px_ = __shfl_up_sync(0xffffffffu, ax1, 1);                           \
    pe_ = (lane == 0) ? (PE_) : pe_;                                           \
    px_ = (lane == 0) ? (PX_) : px_;                                           \
    float nae0_ = EMB0.x * fmaf(pe_, teeW[S_], px_ * txeW[S_]);                \
    float nax0_ = EMB0.y * fmaf(ae0, tex0, ax0 * txx0);                        \
    float nae1_ = EMB1.x * fmaf(ae0, tee1, ax0 * txe1);                        \
    float nax1_ = EMB1.y * fmaf(ae1, tex1, ax1 * txx1);                        \
    const float* tp_ = tab + ((T_) + 2) * 8;                                   \
    EMB0 = *(const float2*)(tp_ + so0);                                        \
    EMB1 = *(const float2*)(tp_ + so1);                                        \
    ae0 = nae0_; ax0 = nax0_; ae1 = nae1_; ax1 = nax1_;                        \
    sts128v_pred(&rprod[(T_)],                                                 \
                 make_float4(ae1, ax1, __int_as_float(e), 0.f),                \
                 pubmask & (int)((T_) <= lenm2));                              \
} while (0)

extern "C" __global__ void __launch_bounds__(256, 1)
ctccrf_fused(const float* __restrict__ em,      // (B,T,8)
             const float* __restrict__ trans,   // (8,8)
             const float* __restrict__ bos,     // (8)
             const float* __restrict__ eos,     // (8)
             const int*   __restrict__ lengths, // (B)
             const int*   __restrict__ targets, // (B,L)
             const int*   __restrict__ tlens,   // (B)
             float* __restrict__ out,
             int B, int T, int L)
{
    extern __shared__ char dsm[];
    __shared__ float s_scratch[MAXB];
    __shared__ int   s_flag;
    const int tid = threadIdx.x;
    const int RNn = T - 1;
    float4* dring = (float4*)dsm;                          // [3][T-1] boundary slots
    float*  tab   = (float*)(dsm + (size_t)3 * RNn * 16);  // [T+4][8] exp-emission table

    if ((int)blockIdx.x < B) {
        const int b = blockIdx.x;
        // ---------- init: ring sentinels + exp-emission table (all 256 threads) ----------
        const float NANSENT = __int_as_float(0x7fc00000);
        for (int i = tid; i < 3 * RNn; i += 256)
            dring[i] = make_float4(NANSENT, 0.f, 0.f, 0.f);
        {
            const float* emb = em + (size_t)b * T * 8;
            for (int f = tid; f < T; f += 256) {
                float4 lo = __ldg((const float4*)(emb + f * 8));
                float4 hi = __ldg((const float4*)(emb + f * 8 + 4));
                float v0 = ex2f_(lo.x * LOG2E_F), v1 = ex2f_(lo.y * LOG2E_F);
                float v2 = ex2f_(lo.z * LOG2E_F), v3 = ex2f_(lo.w * LOG2E_F);
                float v4 = ex2f_(hi.x * LOG2E_F), v5 = ex2f_(hi.y * LOG2E_F);
                float v6 = ex2f_(hi.z * LOG2E_F), v7 = ex2f_(hi.w * LOG2E_F);
                // pair-interleaved: [s0,s4, s1,s5, s2,s6, s3,s7]
                *(float4*)(tab + f * 8)     = make_float4(v0, v4, v1, v5);
                *(float4*)(tab + f * 8 + 4) = make_float4(v2, v6, v3, v7);
            }
        }
        __syncthreads();

        if (tid < 128) {
            // ------- Numerator: 4 worker warps (4 SMSPs), 2 targets/thread -------
            const int lane = tid & 31;
            const int warp = tid >> 5;          // 0..3
            const int u0 = warp * 64 + 2 * lane, u1 = u0 + 1;

            const int len = lengths[b];
            const int lenm2 = len - 2;
            const int tg0 = __ldg(targets + b * L + u0);
            const int tg1 = __ldg(targets + b * L + u1);
            const int so0 = 2 * tg0, so1 = 2 * tg1;
            const int tgp0 = (u0 == 0) ? tg0 : __ldg(targets + b * L + u0 - 1);
            const int pubmask = (int)(lane == 31) & (int)(warp < 3);

            // transitions (linear)
            const float tee0f = __expf(__ldg(trans + tgp0 * 8 + tg0));
            const float txe0f = __expf(__ldg(trans + (tgp0 + 4) * 8 + tg0));
            const float tee0b = (u0 == 0) ? 0.f : tee0f;
            const float txe0b = (u0 == 0) ? 0.f : txe0f;
            const float tex0  = __expf(__ldg(trans + tg0 * 8 + tg0 + 4));
            const float txx0  = __expf(__ldg(trans + (tg0 + 4) * 8 + tg0 + 4));
            const float tee1  = __expf(__ldg(trans + tg0 * 8 + tg1));        // prev of u1 is u0
            const float txe1  = __expf(__ldg(trans + (tg0 + 4) * 8 + tg1));
            const float tex1  = __expf(__ldg(trans + tg1 * 8 + tg1 + 4));
            const float txx1  = __expf(__ldg(trans + (tg1 + 4) * 8 + tg1 + 4));

            float ae0 = (u0 == 0) ? __expf(__ldg(bos + tg0) + __ldg(em + (size_t)b * T * 8 + tg0)) : 0.f;
            float ax0 = 0.f, ae1 = 0.f, ax1 = 0.f;
            int e = 0;
            int zf = (u0 != 0);                 // all-four-zero flag

            float4*       rprod = dring + (size_t)((warp < 3) ? warp : 0) * RNn;
            const float4* rcons = dring + (size_t)((warp > 0) ? (warp - 1) : 0) * RNn;

            // publish initial boundary (time 0)
            if (lane == 31 && warp < 3)
                sts128v(&rprod[0], make_float4(ae1, ax1, __int_as_float(0), 0.f));

            // emission buffers: emc = frame 1, emn = frame 2 (table padded, no clamp)
            float2 emc0, emc1, emn0, emn1;
            emc0 = *(const float2*)(tab + 8 + so0);
            emc1 = *(const float2*)(tab + 8 + so1);
            emn0 = *(const float2*)(tab + 16 + so0);
            emn1 = *(const float2*)(tab + 16 + so1);

            float teeW[4], txeW[4];
            float4 cur0 = make_float4(0.f,0.f,0.f,0.f), cur1 = cur0, cur2 = cur0, cur3 = cur0;
            float4 nxt0 = cur0, nxt1 = cur0, nxt2 = cur0, nxt3 = cur0;
            if (warp > 0) {
                cur0 = lds128v(&rcons[0]);
                cur1 = lds128v(&rcons[min(1, lenm2)]);
                cur2 = lds128v(&rcons[min(2, lenm2)]);
                cur3 = lds128v(&rcons[min(3, lenm2)]);
            }
            int eprev_ = 0;

            int t = 1;
            for (; t + 3 < len; t += 4) {
                if (warp > 0) {
                    while (isnanf_(cur0.x) | isnanf_(cur1.x) | isnanf_(cur2.x) | isnanf_(cur3.x)) {
                        cur0 = lds128v(&rcons[t - 1]);
                        cur1 = lds128v(&rcons[t]);
                        cur2 = lds128v(&rcons[t + 1]);
                        cur3 = lds128v(&rcons[t + 2]);
                    }
                    nxt0 = lds128v(&rcons[min(t + 3, lenm2)]);
                    nxt1 = lds128v(&rcons[min(t + 4, lenm2)]);
                    nxt2 = lds128v(&rcons[min(t + 5, lenm2)]);
                    nxt3 = lds128v(&rcons[min(t + 6, lenm2)]);
                }
                // group-top exponent admin (off the per-step chain)
                eprev_ = __shfl_up_sync(0xffffffffu, e, 1);
                int eup_ = (lane == 0) ? ((warp > 0) ? __float_as_int(cur0.z) : e) : eprev_;
                e = zf ? eup_ : e;
                FOLD(0, cur0.z); FOLD(1, cur1.z); FOLD(2, cur2.z); FOLD(3, cur3.z);

                NSTEP(t,     emc0, emc1, cur0.x, cur0.y, 0);
                NSTEP(t + 1, emn0, emn1, cur1.x, cur1.y, 1);
                NSTEP(t + 2, emc0, emc1, cur2.x, cur2.y, 2);
                NSTEP(t + 3, emn0, emn1, cur3.x, cur3.y, 3);

                // group rescale
                float m_ = fmaxf(fmaxf(ae0, ax0), fmaxf(ae1, ax1));
                int mb_ = __float_as_int(m_);
                zf = (mb_ == 0);
                int ei_ = zf ? 0 : ((mb_ >> 23) - 127);
                float fr_ = __int_as_float((127 - ei_) << 23);
                ae0 *= fr_; ax0 *= fr_; ae1 *= fr_; ax1 *= fr_;
                e += ei_;

                cur0 = nxt0; cur1 = nxt1; cur2 = nxt2; cur3 = nxt3;
            }
            // remainder (<=3 steps; len uniform across block)
            eprev_ = __shfl_up_sync(0xffffffffu, e, 1);
            if (t < len) {
                float4 bb = make_float4(0.f,0.f,0.f,0.f);
                if (warp > 0) { do { bb = lds128v(&rcons[t - 1]); } while (isnanf_(bb.x)); }
                FOLD(0, bb.z);
                NSTEP(t, emc0, emc1, bb.x, bb.y, 0); t++;
            }
            if (t < len) {
                float4 bb = make_float4(0.f,0.f,0.f,0.f);
                if (warp > 0) { do { bb = lds128v(&rcons[t - 1]); } while (isnanf_(bb.x)); }
                FOLD(0, bb.z);
                NSTEP(t, emn0, emn1, bb.x, bb.y, 0); t++;
            }
            if (t < len) {
                float4 bb = make_float4(0.f,0.f,0.f,0.f);
                if (warp > 0) { do { bb = lds128v(&rcons[t - 1]); } while (isnanf_(bb.x)); }
                FOLD(0, bb.z);
                NSTEP(t, emc0, emc1, bb.x, bb.y, 0); t++;
            }

            // ---- final logsumexp for the terminal target ----
            const int tl = __ldg(tlens + b);
            const int uf = tl - 1;
            if (u0 == uf) {
                float fe2 = (ae0 > 0.f ? lg2f_(ae0) : NEGF) + (float)e + __ldg(eos + tg0) * LOG2E_F;
                float fx2 = (ax0 > 0.f ? lg2f_(ax0) : NEGF) + (float)e + __ldg(eos + tg0 + 4) * LOG2E_F;
                g_num[b] = lae2(fe2, fx2) * LN2_F;
            }
            if (u1 == uf) {
                float fe2 = (ae1 > 0.f ? lg2f_(ae1) : NEGF) + (float)e + __ldg(eos + tg1) * LOG2E_F;
                float fx2 = (ax1 > 0.f ? lg2f_(ax1) : NEGF) + (float)e + __ldg(eos + tg1 + 4) * LOG2E_F;
                g_num[b] = lae2(fe2, fx2) * LN2_F;
            }
        }
    } else {
        // ------------- Denominator Phase A: chunked 8x8 linear-space scan -------------
        const int db = blockIdx.x - B;          // batch (grid is exactly 2B)
        const int c = tid >> 3;                 // chunk 0..31
        const int i = tid & 7;                  // row of chunk matrix
        const int len = lengths[db];
        const int C = (T - 1 + NCH - 1) / NCH;

        float E[64];
        #pragma unroll
        for (int k = 0; k < 64; ++k) E[k] = __expf(__ldg(trans + k));

        float r[8];
        #pragma unroll
        for (int j = 0; j < 8; ++j) r[j] = (j == i) ? 1.0f : 0.0f;
        float off = 0.0f;

        const int t0 = 1 + c * C;
        const int t1 = min(t0 + C, len);
        const float* emb = em + (size_t)db * T * 8;

        for (int t = t0; t < t1; ++t) {
            float4 lo = __ldg((const float4*)(emb + t * 8));
            float4 hi = __ldg((const float4*)(emb + t * 8 + 4));
            float Em[8];
            Em[0] = __expf(lo.x); Em[1] = __expf(lo.y);
            Em[2] = __expf(lo.z); Em[3] = __expf(lo.w);
            Em[4] = __expf(hi.x); Em[5] = __expf(hi.y);
            Em[6] = __expf(hi.z); Em[7] = __expf(hi.w);

            float s[8];
            #pragma unroll
            for (int j = 0; j < 8; ++j) {
                float acc = r[0] * E[0 * 8 + j];
                #pragma unroll
                for (int kk = 1; kk < 8; ++kk) acc = fmaf(r[kk], E[kk * 8 + j], acc);
                s[j] = acc * Em[j];
            }
            #pragma unroll
            for (int j = 0; j < 8; ++j) r[j] = s[j];

            if (((t - t0) & 3) == 3) {
                float m = r[0];
                #pragma unroll
                for (int j = 1; j < 8; ++j) m = fmaxf(m, r[j]);
                float inv = __fdividef(1.0f, m);
                off += __logf(m);
                #pragma unroll
                for (int j = 0; j < 8; ++j) r[j] *= inv;
            }
        }

        #pragma unroll
        for (int j = 0; j < 8; ++j) {
            float lv = (r[j] > 0.0f) ? (__logf(r[j]) + off) : NEGF;
            g_LP[(((db * NCH) + c) * 8 + j) * 8 + i] = lv;
        }
    }

    // ---------------- Fused finish: last block folds chunks + reduces ----------------
    __threadfence();
    __syncthreads();
    if (tid == 0) {
        unsigned old = atomicAdd(&g_done, 1u);
        s_flag = (old == (unsigned)(2 * B - 1));
    }
    __syncthreads();
    if (s_flag) {
        __threadfence();
        const int  bq = min(tid >> 3, B - 1);   // clamp so all 256 threads run shfls
        const int  j  = tid & 7;
        const bool active = (tid >> 3) < B;

        float alpha = __ldg(bos + j) + __ldg(em + (size_t)bq * T * 8 + j);  // natural log
        const float* base = g_LP + (size_t)bq * NCH * 64 + j * 8;
        float4 plo[4], phi[4];
        #pragma unroll
        for (int kk = 0; kk < 4; ++kk) {
            plo[kk] = __ldg((const float4*)(base + kk * 64));
            phi[kk] = __ldg((const float4*)(base + kk * 64 + 4));
        }
        #pragma unroll 4
        for (int c = 0; c < NCH; ++c) {
            float4 lo = plo[c & 3], hi = phi[c & 3];
            int cn = c + 4;
            if (cn < NCH) {
                plo[c & 3] = __ldg((const float4*)(base + cn * 64));
                phi[c & 3] = __ldg((const float4*)(base + cn * 64 + 4));
            }
            float M[8] = {lo.x, lo.y, lo.z, lo.w, hi.x, hi.y, hi.z, hi.w};
            float v[8], m = -3.0e38f;
            #pragma unroll
            for (int i2 = 0; i2 < 8; ++i2) {
                float ai = __shfl_sync(0xffffffffu, alpha, i2, 8);
                v[i2] = ai + M[i2];
                m = fmaxf(m, v[i2]);
            }
            float s = 0.0f;
            #pragma unroll
            for (int i2 = 0; i2 < 8; ++i2) s += ex2f_((v[i2] - m) * LOG2E_F);
            alpha = m + lg2f_(s) * LN2_F;
        }
        float f = alpha + __ldg(eos + j);
        float m = f;
        #pragma unroll
        for (int d = 4; d >= 1; d >>= 1) m = fmaxf(m, __shfl_xor_sync(0xffffffffu, m, d, 8));
        float s = ex2f_((f - m) * LOG2E_F);
        #pragma unroll
        for (int d = 4; d >= 1; d >>= 1) s += __shfl_xor_sync(0xffffffffu, s, d, 8);
        float den = m + lg2f_(s) * LN2_F;

        if (active && j == 0) s_scratch[tid >> 3] = den - g_num[bq];
        __syncthreads();
        if (tid == 0) {
            float acc = 0.0f;
            for (int bb = 0; bb < B; ++bb) acc += s_scratch[bb];
            out[0] = acc / (float)B;
            g_done = 0;                         // reset for next graph replay
        }
    }
}

extern "C" void kernel_launch(void* const* d_in, const int* in_sizes, int n_in,
                              void* d_out, int out_size)
{
    const float* em     = (const float*)d_in[0];  // (B,T,8)
    const float* trans  = (const float*)d_in[1];  // (8,8)
    const float* bos    = (const float*)d_in[2];  // (8)
    const float* eos    = (const float*)d_in[3];  // (8)
    const int*   lens   = (const int*)  d_in[4];  // (B)
    const int*   tgts   = (const int*)  d_in[5];  // (B,L)
    const int*   tlens  = (const int*)  d_in[6];  // (B)
    float* out = (float*)d_out;

    const int B = in_sizes[4];                 // 16
    const int T = in_sizes[0] / (B * 8);       // 2048
    const int L = in_sizes[5] / B;             // 256

    // dynamic smem: boundary rings [3][T-1] float4 + padded exp-emission table [T+4][8]
    const size_t smem = (size_t)3 * (T - 1) * sizeof(float4)
                      + (size_t)(T + 4) * 8 * sizeof(float);
    cudaFuncSetAttribute(ctccrf_fused, cudaFuncAttributeMaxDynamicSharedMemorySize, (int)smem);

    // Blocks [0,B): numerator (4 worker warps, group-amortized exponent handling).
    // Blocks [B,2B): denominator phase A. Last-done block runs the finish fold.
    ctccrf_fused<<<2 * B, 256, smem>>>(em, trans, bos, eos, lens, tgts, tlens, out, B, T, L);
}